// round 13
// baseline (speedup 1.0000x reference)
#include <cuda_runtime.h>
#include <cuda_bf16.h>

// Shape fixed by dataset: pred_dT/gt_dT [B, M, M, 4] fp32, Ms [V] int32.
#define B_ 16
#define M_ 1024
#define MM (M_ * M_)                  // 1,048,576 (i,j) pairs per batch slice

#define BLOCKS   4096                 // fine-grained grid: self-balances across SMs
#define THREADS  256

// Persistent device state. Zero at module load; the finalizing block re-zeroes
// it at the end of every launch -> each call (correctness + graph replays)
// starts identical -> deterministic.
__device__ double       g_acc[4];     // [0]=tot_t [1]=tot_s [2]=inter_t [3]=inter_s
__device__ unsigned int g_count;

// Streaming 16B read-only load that BYPASSES L1 allocation. Data is touched
// exactly once; allocating it in L1 only burns l1tex tag/fill bandwidth.
__device__ __forceinline__ float4 ldg_stream_nc(const float4* p) {
    float4 v;
    asm volatile("ld.global.nc.L1::no_allocate.v4.f32 {%0,%1,%2,%3}, [%4];"
                 : "=f"(v.x), "=f"(v.y), "=f"(v.z), "=f"(v.w)
                 : "l"(p));
    return v;
}

// No min-blocks clamp: R9-winning config (unroll 8, regs ~36).
__global__ __launch_bounds__(THREADS)
void pose_loss_fused_kernel(const float4* __restrict__ pred,
                            const float4* __restrict__ gt,
                            const int*    __restrict__ Ms,
                            float*        __restrict__ out) {
    // Pair index within one batch slice; batch accesses stride by MM, so
    // (i, j) -- and the inter/intra mask -- is a per-thread CONSTANT.
    const int tid = blockIdx.x * THREADS + threadIdx.x;   // 0 .. MM-1
    const int i = tid >> 10;          // row token
    const int j = tid & (M_ - 1);     // col token

    // View boundaries from Ms (uniform loads, warp-broadcast).
    const int o1 = __ldg(Ms + 0);
    const int o2 = o1 + __ldg(Ms + 1);
    const int o3 = o2 + __ldg(Ms + 2);
    const int vi = (i >= o1) + (i >= o2) + (i >= o3);
    const int vj = (j >= o1) + (j >= o2) + (j >= o3);
    const bool inter = (vi != vj);

    // Hot loop: unroll 8 (proven best MLP), L1-bypass streaming loads.
    float acc_t = 0.f, acc_s = 0.f;
    const float4* p = pred + tid;
    const float4* g = gt   + tid;
    #pragma unroll 8
    for (int b = 0; b < B_; b++) {
        float4 pv = ldg_stream_nc(p + (size_t)b * MM);
        float4 gv = ldg_stream_nc(g + (size_t)b * MM);
        float d0 = pv.x - gv.x;
        float d1 = pv.y - gv.y;
        float d2 = pv.z - gv.z;
        float d3 = pv.w - gv.w;
        acc_t += d0 * d0 + d1 * d1;
        acc_s += d2 * d2 + d3 * d3;
    }
    // Apply the per-thread-constant mask once.
    const float acc_it = inter ? acc_t : 0.f;
    const float acc_is = inter ? acc_s : 0.f;

    // ---- Block reduction: warp shuffles -> shared -> warp 0 ----
    float tt = acc_t, ts = acc_s, it = acc_it, is = acc_is;
    #pragma unroll
    for (int off = 16; off > 0; off >>= 1) {
        tt += __shfl_down_sync(0xFFFFFFFFu, tt, off);
        ts += __shfl_down_sync(0xFFFFFFFFu, ts, off);
        it += __shfl_down_sync(0xFFFFFFFFu, it, off);
        is += __shfl_down_sync(0xFFFFFFFFu, is, off);
    }
    __shared__ float4 warp_part[THREADS / 32];
    const int lane = threadIdx.x & 31;
    const int wid  = threadIdx.x >> 5;
    if (lane == 0) warp_part[wid] = make_float4(tt, ts, it, is);
    __syncthreads();

    if (wid == 0) {
        float4 v = (lane < THREADS / 32) ? warp_part[lane]
                                         : make_float4(0.f, 0.f, 0.f, 0.f);
        #pragma unroll
        for (int off = 4; off > 0; off >>= 1) {
            v.x += __shfl_down_sync(0xFFFFFFFFu, v.x, off);
            v.y += __shfl_down_sync(0xFFFFFFFFu, v.y, off);
            v.z += __shfl_down_sync(0xFFFFFFFFu, v.z, off);
            v.w += __shfl_down_sync(0xFFFFFFFFu, v.w, off);
        }
        if (lane == 0) {
            atomicAdd(&g_acc[0], (double)v.x);
            atomicAdd(&g_acc[1], (double)v.y);
            atomicAdd(&g_acc[2], (double)v.z);
            atomicAdd(&g_acc[3], (double)v.w);

            __threadfence();
            unsigned prev = atomicAdd(&g_count, 1u);

            if (prev == (unsigned)gridDim.x - 1u) {
                // ---- Last block: finalize the 7 loss scalars ----
                double tot_t   = atomicAdd(&g_acc[0], 0.0);
                double tot_s   = atomicAdd(&g_acc[1], 0.0);
                double inter_t = atomicAdd(&g_acc[2], 0.0);
                double inter_s = atomicAdd(&g_acc[3], 0.0);
                double intra_t = tot_t - inter_t;
                double intra_s = tot_s - inter_s;

                int m0 = __ldg(Ms + 0), m1 = __ldg(Ms + 1),
                    m2 = __ldg(Ms + 2), m3 = __ldg(Ms + 3);
                double sumMs2 = (double)(m0 * m0 + m1 * m1 + m2 * m2 + m3 * m3);
                double diag_count    = sumMs2 * (double)B_;
                double offdiag_count = ((double)M_ * (double)M_ - sumMs2) * (double)B_;

                double li_t = intra_t / diag_count;
                double li_s = intra_s / diag_count;
                double le_t = inter_t / offdiag_count;
                double le_s = inter_s / offdiag_count;

                const double ALPHA_T = 0.5, ALPHA_S = 0.75, ALPHA_TS = 0.5;
                double lt   = ALPHA_T * le_t + (1.0 - ALPHA_T) * li_t;
                double ls   = ALPHA_S * le_s + (1.0 - ALPHA_S) * li_s;
                double loss = ALPHA_TS * lt + (1.0 - ALPHA_TS) * ls;

                out[0] = (float)li_t;
                out[1] = (float)le_t;
                out[2] = (float)li_s;
                out[3] = (float)le_s;
                out[4] = (float)lt;
                out[5] = (float)ls;
                out[6] = (float)loss;

                // ---- Self-clean for the next (graph-replayed) launch ----
                g_acc[0] = 0.0; g_acc[1] = 0.0;
                g_acc[2] = 0.0; g_acc[3] = 0.0;
                atomicExch(&g_count, 0u);
            }
        }
    }
}

extern "C" void kernel_launch(void* const* d_in, const int* in_sizes, int n_in,
                              void* d_out, int out_size) {
    const float4* pred = (const float4*)d_in[0];
    const float4* gt   = (const float4*)d_in[1];
    const int*    Ms   = (const int*)d_in[2];
    float*        out  = (float*)d_out;

    pose_loss_fused_kernel<<<BLOCKS, THREADS>>>(pred, gt, Ms, out);
}

// round 15
// speedup vs baseline: 1.0074x; 1.0074x over previous
#include <cuda_runtime.h>
#include <cuda_bf16.h>

// Shape fixed by dataset: pred_dT/gt_dT [B, M, M, 4] fp32, Ms [V] int32.
#define B_ 16
#define M_ 1024
#define MM (M_ * M_)                  // 1,048,576 (i,j) pairs per batch slice

#define BLOCKS   4096                 // fine-grained grid: self-balances across SMs
#define THREADS  256

// Persistent device state. Zero at module load; the finalizing block re-zeroes
// it at the end of every launch -> each call (correctness + graph replays)
// starts identical -> deterministic.
__device__ double       g_acc[4];     // [0]=tot_t [1]=tot_s [2]=inter_t [3]=inter_s
__device__ unsigned int g_count;

// R9 winning configuration: unroll 8, plain __ldg, no min-blocks clamp
// (regs ~36 -> ptxas software-pipelines the load stream; measured 84.5 us,
// 6.27 TB/s = the B300 LTS chip cap. All other traversal/occupancy/L1 variants
// measured equal or worse; this kernel is at the memory-system ceiling).
__global__ __launch_bounds__(THREADS)
void pose_loss_fused_kernel(const float4* __restrict__ pred,
                            const float4* __restrict__ gt,
                            const int*    __restrict__ Ms,
                            float*        __restrict__ out) {
    // Pair index within one batch slice; the batch loop strides by MM, so
    // (i, j) -- and the inter/intra mask -- is a per-thread CONSTANT.
    const int tid = blockIdx.x * THREADS + threadIdx.x;   // 0 .. MM-1
    const int i = tid >> 10;          // row token
    const int j = tid & (M_ - 1);     // col token

    // View boundaries from Ms (uniform loads, warp-broadcast).
    const int o1 = __ldg(Ms + 0);
    const int o2 = o1 + __ldg(Ms + 1);
    const int o3 = o2 + __ldg(Ms + 2);
    const int vi = (i >= o1) + (i >= o2) + (i >= o3);
    const int vj = (j >= o1) + (j >= o2) + (j >= o3);
    const bool inter = (vi != vj);

    // Hot loop: 2x LDG.128 + diff-squares per batch slice, unroll 8.
    float acc_t = 0.f, acc_s = 0.f;
    const float4* p = pred + tid;
    const float4* g = gt   + tid;
    #pragma unroll 8
    for (int b = 0; b < B_; b++) {
        float4 pv = __ldg(p + (size_t)b * MM);
        float4 gv = __ldg(g + (size_t)b * MM);
        float d0 = pv.x - gv.x;
        float d1 = pv.y - gv.y;
        float d2 = pv.z - gv.z;
        float d3 = pv.w - gv.w;
        acc_t += d0 * d0 + d1 * d1;
        acc_s += d2 * d2 + d3 * d3;
    }
    // Apply the per-thread-constant mask once.
    const float acc_it = inter ? acc_t : 0.f;
    const float acc_is = inter ? acc_s : 0.f;

    // ---- Block reduction: warp shuffles -> shared -> warp 0 ----
    float tt = acc_t, ts = acc_s, it = acc_it, is = acc_is;
    #pragma unroll
    for (int off = 16; off > 0; off >>= 1) {
        tt += __shfl_down_sync(0xFFFFFFFFu, tt, off);
        ts += __shfl_down_sync(0xFFFFFFFFu, ts, off);
        it += __shfl_down_sync(0xFFFFFFFFu, it, off);
        is += __shfl_down_sync(0xFFFFFFFFu, is, off);
    }
    __shared__ float4 warp_part[THREADS / 32];
    const int lane = threadIdx.x & 31;
    const int wid  = threadIdx.x >> 5;
    if (lane == 0) warp_part[wid] = make_float4(tt, ts, it, is);
    __syncthreads();

    if (wid == 0) {
        float4 v = (lane < THREADS / 32) ? warp_part[lane]
                                         : make_float4(0.f, 0.f, 0.f, 0.f);
        #pragma unroll
        for (int off = 4; off > 0; off >>= 1) {
            v.x += __shfl_down_sync(0xFFFFFFFFu, v.x, off);
            v.y += __shfl_down_sync(0xFFFFFFFFu, v.y, off);
            v.z += __shfl_down_sync(0xFFFFFFFFu, v.z, off);
            v.w += __shfl_down_sync(0xFFFFFFFFu, v.w, off);
        }
        if (lane == 0) {
            atomicAdd(&g_acc[0], (double)v.x);
            atomicAdd(&g_acc[1], (double)v.y);
            atomicAdd(&g_acc[2], (double)v.z);
            atomicAdd(&g_acc[3], (double)v.w);

            __threadfence();
            unsigned prev = atomicAdd(&g_count, 1u);

            if (prev == (unsigned)gridDim.x - 1u) {
                // ---- Last block: finalize the 7 loss scalars ----
                double tot_t   = atomicAdd(&g_acc[0], 0.0);
                double tot_s   = atomicAdd(&g_acc[1], 0.0);
                double inter_t = atomicAdd(&g_acc[2], 0.0);
                double inter_s = atomicAdd(&g_acc[3], 0.0);
                double intra_t = tot_t - inter_t;
                double intra_s = tot_s - inter_s;

                int m0 = __ldg(Ms + 0), m1 = __ldg(Ms + 1),
                    m2 = __ldg(Ms + 2), m3 = __ldg(Ms + 3);
                double sumMs2 = (double)(m0 * m0 + m1 * m1 + m2 * m2 + m3 * m3);
                double diag_count    = sumMs2 * (double)B_;
                double offdiag_count = ((double)M_ * (double)M_ - sumMs2) * (double)B_;

                double li_t = intra_t / diag_count;
                double li_s = intra_s / diag_count;
                double le_t = inter_t / offdiag_count;
                double le_s = inter_s / offdiag_count;

                const double ALPHA_T = 0.5, ALPHA_S = 0.75, ALPHA_TS = 0.5;
                double lt   = ALPHA_T * le_t + (1.0 - ALPHA_T) * li_t;
                double ls   = ALPHA_S * le_s + (1.0 - ALPHA_S) * li_s;
                double loss = ALPHA_TS * lt + (1.0 - ALPHA_TS) * ls;

                out[0] = (float)li_t;
                out[1] = (float)le_t;
                out[2] = (float)li_s;
                out[3] = (float)le_s;
                out[4] = (float)lt;
                out[5] = (float)ls;
                out[6] = (float)loss;

                // ---- Self-clean for the next (graph-replayed) launch ----
                g_acc[0] = 0.0; g_acc[1] = 0.0;
                g_acc[2] = 0.0; g_acc[3] = 0.0;
                atomicExch(&g_count, 0u);
            }
        }
    }
}

extern "C" void kernel_launch(void* const* d_in, const int* in_sizes, int n_in,
                              void* d_out, int out_size) {
    const float4* pred = (const float4*)d_in[0];
    const float4* gt   = (const float4*)d_in[1];
    const int*    Ms   = (const int*)d_in[2];
    float*        out  = (float*)d_out;

    pose_loss_fused_kernel<<<BLOCKS, THREADS>>>(pred, gt, Ms, out);
}

// round 17
// speedup vs baseline: 1.0335x; 1.0259x over previous
#include <cuda_runtime.h>
#include <cuda_bf16.h>

// Shape fixed by dataset: pred_dT/gt_dT [B, M, M, 4] fp32, Ms [V] int32.
#define B_ 16
#define M_ 1024
#define MM (M_ * M_)                  // 1,048,576 (i,j) pairs per batch slice

#define THREADS  512
#define BLOCKS   (MM / THREADS)       // 2048
#define NWARPS   (THREADS / 32)       // 16

// Persistent device state. Zero at module load; the finalizing block re-zeroes
// it at the end of every launch -> each call (correctness + graph replays)
// starts identical -> deterministic.
__device__ double       g_acc[4];     // [0]=tot_t [1]=tot_s [2]=inter_t [3]=inter_s
__device__ unsigned int g_count;

// Ceiling config (R9): unroll 8, plain __ldg, no min-blocks clamp. The only
// variable this round is block shape (512 vs 256) -- fewer CTAs, fewer block
// reductions, different per-SM CTA mix.
__global__ __launch_bounds__(THREADS)
void pose_loss_fused_kernel(const float4* __restrict__ pred,
                            const float4* __restrict__ gt,
                            const int*    __restrict__ Ms,
                            float*        __restrict__ out) {
    // Pair index within one batch slice; the batch loop strides by MM, so
    // (i, j) -- and the inter/intra mask -- is a per-thread CONSTANT.
    const int tid = blockIdx.x * THREADS + threadIdx.x;   // 0 .. MM-1
    const int i = tid >> 10;          // row token
    const int j = tid & (M_ - 1);     // col token

    // View boundaries from Ms (uniform loads, warp-broadcast).
    const int o1 = __ldg(Ms + 0);
    const int o2 = o1 + __ldg(Ms + 1);
    const int o3 = o2 + __ldg(Ms + 2);
    const int vi = (i >= o1) + (i >= o2) + (i >= o3);
    const int vj = (j >= o1) + (j >= o2) + (j >= o3);
    const bool inter = (vi != vj);

    // Hot loop: 2x LDG.128 + diff-squares per batch slice, unroll 8.
    float acc_t = 0.f, acc_s = 0.f;
    const float4* p = pred + tid;
    const float4* g = gt   + tid;
    #pragma unroll 8
    for (int b = 0; b < B_; b++) {
        float4 pv = __ldg(p + (size_t)b * MM);
        float4 gv = __ldg(g + (size_t)b * MM);
        float d0 = pv.x - gv.x;
        float d1 = pv.y - gv.y;
        float d2 = pv.z - gv.z;
        float d3 = pv.w - gv.w;
        acc_t += d0 * d0 + d1 * d1;
        acc_s += d2 * d2 + d3 * d3;
    }
    // Apply the per-thread-constant mask once.
    const float acc_it = inter ? acc_t : 0.f;
    const float acc_is = inter ? acc_s : 0.f;

    // ---- Block reduction: warp shuffles -> shared -> warp 0 ----
    float tt = acc_t, ts = acc_s, it = acc_it, is = acc_is;
    #pragma unroll
    for (int off = 16; off > 0; off >>= 1) {
        tt += __shfl_down_sync(0xFFFFFFFFu, tt, off);
        ts += __shfl_down_sync(0xFFFFFFFFu, ts, off);
        it += __shfl_down_sync(0xFFFFFFFFu, it, off);
        is += __shfl_down_sync(0xFFFFFFFFu, is, off);
    }
    __shared__ float4 warp_part[NWARPS];
    const int lane = threadIdx.x & 31;
    const int wid  = threadIdx.x >> 5;
    if (lane == 0) warp_part[wid] = make_float4(tt, ts, it, is);
    __syncthreads();

    if (wid == 0) {
        float4 v = (lane < NWARPS) ? warp_part[lane]
                                   : make_float4(0.f, 0.f, 0.f, 0.f);
        #pragma unroll
        for (int off = 8; off > 0; off >>= 1) {
            v.x += __shfl_down_sync(0xFFFFFFFFu, v.x, off);
            v.y += __shfl_down_sync(0xFFFFFFFFu, v.y, off);
            v.z += __shfl_down_sync(0xFFFFFFFFu, v.z, off);
            v.w += __shfl_down_sync(0xFFFFFFFFu, v.w, off);
        }
        if (lane == 0) {
            atomicAdd(&g_acc[0], (double)v.x);
            atomicAdd(&g_acc[1], (double)v.y);
            atomicAdd(&g_acc[2], (double)v.z);
            atomicAdd(&g_acc[3], (double)v.w);

            __threadfence();
            unsigned prev = atomicAdd(&g_count, 1u);

            if (prev == (unsigned)gridDim.x - 1u) {
                // ---- Last block: finalize the 7 loss scalars ----
                double tot_t   = atomicAdd(&g_acc[0], 0.0);
                double tot_s   = atomicAdd(&g_acc[1], 0.0);
                double inter_t = atomicAdd(&g_acc[2], 0.0);
                double inter_s = atomicAdd(&g_acc[3], 0.0);
                double intra_t = tot_t - inter_t;
                double intra_s = tot_s - inter_s;

                int m0 = __ldg(Ms + 0), m1 = __ldg(Ms + 1),
                    m2 = __ldg(Ms + 2), m3 = __ldg(Ms + 3);
                double sumMs2 = (double)(m0 * m0 + m1 * m1 + m2 * m2 + m3 * m3);
                double diag_count    = sumMs2 * (double)B_;
                double offdiag_count = ((double)M_ * (double)M_ - sumMs2) * (double)B_;

                double li_t = intra_t / diag_count;
                double li_s = intra_s / diag_count;
                double le_t = inter_t / offdiag_count;
                double le_s = inter_s / offdiag_count;

                const double ALPHA_T = 0.5, ALPHA_S = 0.75, ALPHA_TS = 0.5;
                double lt   = ALPHA_T * le_t + (1.0 - ALPHA_T) * li_t;
                double ls   = ALPHA_S * le_s + (1.0 - ALPHA_S) * li_s;
                double loss = ALPHA_TS * lt + (1.0 - ALPHA_TS) * ls;

                out[0] = (float)li_t;
                out[1] = (float)le_t;
                out[2] = (float)li_s;
                out[3] = (float)le_s;
                out[4] = (float)lt;
                out[5] = (float)ls;
                out[6] = (float)loss;

                // ---- Self-clean for the next (graph-replayed) launch ----
                g_acc[0] = 0.0; g_acc[1] = 0.0;
                g_acc[2] = 0.0; g_acc[3] = 0.0;
                atomicExch(&g_count, 0u);
            }
        }
    }
}

extern "C" void kernel_launch(void* const* d_in, const int* in_sizes, int n_in,
                              void* d_out, int out_size) {
    const float4* pred = (const float4*)d_in[0];
    const float4* gt   = (const float4*)d_in[1];
    const int*    Ms   = (const int*)d_in[2];
    float*        out  = (float*)d_out;

    pose_loss_fused_kernel<<<BLOCKS, THREADS>>>(pred, gt, Ms, out);
}